// round 4
// baseline (speedup 1.0000x reference)
#include <cuda_runtime.h>
#include <cstdint>

#define NSEG 128
#define FEAT 64
#define LATENT 512
#define H1DIM 256
#define H2DIM 512
#define OUTDIM (2048*3)

// ---------------- scratch (no allocs allowed) ----------------
__device__ unsigned g_pool[NSEG * FEAT];       // ordered-uint encoded running max
__device__ float    g_lat[NSEG * LATENT];
__device__ float    g_h1[NSEG * H1DIM];
__device__ float    g_h2[NSEG * H2DIM];

// monotonic float<->uint encoding so unsigned atomicMax == float max
__device__ __forceinline__ unsigned ford(float f) {
    unsigned u = __float_as_uint(f);
    return (u & 0x80000000u) ? ~u : (u | 0x80000000u);
}
__device__ __forceinline__ float unford(unsigned u) {
    unsigned b = (u & 0x80000000u) ? (u ^ 0x80000000u) : ~u;
    return __uint_as_float(b);
}

// ---------------- kernel 0: init pool to ford(-inf) ----------------
__global__ void k_init() {
    int i = blockIdx.x * blockDim.x + threadIdx.x;
    if (i < NSEG * FEAT) g_pool[i] = 0x007FFFFFu;   // ford(-inf)
}

// ---------------- kernel 1: segment max ----------------
// blockDim=256: 8 row-lanes x 32 col-pairs. Each warp streams whole rows.
// batch dtype (int32 vs int64) detected at runtime:
//   word[n-1] (safe to read in both layouts) is the last sorted id (!=0) for
//   int32, or the zero hi-word of element (n-1)/2 for int64.
template<bool IS64>
__device__ __forceinline__ void segmax_body(const float* __restrict__ feat,
                                            const void* __restrict__ batch, int n) {
    const int*       b32 = (const int*)batch;
    const long long* b64 = (const long long*)batch;
    int chunk = (n + gridDim.x - 1) / gridDim.x;
    int r0 = blockIdx.x * chunk;
    int r1 = min(n, r0 + chunk);
    int lr = threadIdx.x >> 5;   // 0..7
    int cp = threadIdx.x & 31;   // col pair
    float mx = __int_as_float(0xff800000), my = mx;
    int cur = -1;
    for (int r = r0 + lr; r < r1; r += 8) {
        int s = IS64 ? (int)b64[r] : b32[r];
        float2 v = ((const float2*)(feat + (size_t)r * FEAT))[cp];
        if (s != cur) {
            if ((unsigned)cur < NSEG) {
                atomicMax(&g_pool[cur * FEAT + 2 * cp],     ford(mx));
                atomicMax(&g_pool[cur * FEAT + 2 * cp + 1], ford(my));
            }
            cur = s; mx = v.x; my = v.y;
        } else {
            mx = fmaxf(mx, v.x); my = fmaxf(my, v.y);
        }
    }
    if ((unsigned)cur < NSEG) {
        atomicMax(&g_pool[cur * FEAT + 2 * cp],     ford(mx));
        atomicMax(&g_pool[cur * FEAT + 2 * cp + 1], ford(my));
    }
}

__global__ void k_segmax(const float* __restrict__ feat,
                         const void* __restrict__ batch, int n) {
    bool is32 = (((const int*)batch)[n - 1] != 0);
    if (is32) segmax_body<false>(feat, batch, n);
    else      segmax_body<true >(feat, batch, n);
}

// ---------------- kernel 2: LayerNorm(64) + proj 64->512 ----------------
__global__ void k_lnproj(const float* __restrict__ lng, const float* __restrict__ lnb,
                         const float* __restrict__ W,   const float* __restrict__ pb) {
    int row = blockIdx.x;
    int t = threadIdx.x;   // 0..63
    __shared__ float xn[FEAT];
    __shared__ float red[4];
    float x = unford(g_pool[row * FEAT + t]);
    float s = x, q = x * x;
    #pragma unroll
    for (int o = 16; o; o >>= 1) {
        s += __shfl_xor_sync(0xffffffffu, s, o);
        q += __shfl_xor_sync(0xffffffffu, q, o);
    }
    if ((t & 31) == 0) { red[t >> 5] = s; red[2 + (t >> 5)] = q; }
    __syncthreads();
    float mu  = (red[0] + red[1]) * (1.0f / FEAT);
    float var = (red[2] + red[3]) * (1.0f / FEAT) - mu * mu;
    float rs  = rsqrtf(var + 1e-5f);
    xn[t] = (x - mu) * rs * lng[t] + lnb[t];
    __syncthreads();
    float acc[8];
    #pragma unroll
    for (int m = 0; m < 8; m++) acc[m] = pb[t + 64 * m];
    #pragma unroll 4
    for (int k = 0; k < FEAT; k++) {
        float xv = xn[k];
        #pragma unroll
        for (int m = 0; m < 8; m++)
            acc[m] = fmaf(xv, W[k * LATENT + t + 64 * m], acc[m]);
    }
    #pragma unroll
    for (int m = 0; m < 8; m++) g_lat[row * LATENT + t + 64 * m] = acc[m];
}

// ---------------- kernel 3: plain fp32 tiled GEMM  C = [relu](A*B + bias) ----------------
// MODE 0: g_lat->g_h1 (relu), MODE 1: g_h1->g_h2 (relu), MODE 2: g_h2->Cout (no relu)
// BM=64 BN=32 BK=32, 256 threads; each thread computes 4 rows x 2 cols.
template<int MODE>
__launch_bounds__(256)
__global__ void k_gemm(const float* __restrict__ Bw,
                       const float* __restrict__ bias, float* __restrict__ Cout,
                       int N, int K) {
    const float* A = (MODE == 0) ? g_lat : (MODE == 1) ? g_h1 : g_h2;
    float*       C = (MODE == 0) ? g_h1  : (MODE == 1) ? g_h2 : Cout;
    constexpr bool RELU = (MODE != 2);

    constexpr int BM = 64, BN = 32, BK = 32;
    __shared__ __align__(16) float As[BK][BM];
    __shared__ __align__(16) float Bs[BK][BN];
    int tid = threadIdx.x;
    int tx = tid & 15;       // 16 col-groups of 2
    int ty = tid >> 4;       // 16 row-groups of 4
    int bm0 = blockIdx.y * BM, bn0 = blockIdx.x * BN;
    int c0 = bn0 + tx * 2;

    float acc[4][2];
    {
        float b0 = bias[c0], b1 = bias[c0 + 1];
        #pragma unroll
        for (int i = 0; i < 4; i++) { acc[i][0] = b0; acc[i][1] = b1; }
    }

    for (int k0 = 0; k0 < K; k0 += BK) {
        // A tile: 64x32 floats, loaded float4, stored transposed
        #pragma unroll
        for (int l = tid; l < BM * BK / 4; l += 256) {
            int ar = l >> 3, ak = (l & 7) * 4;
            float4 v = *(const float4*)&A[(size_t)(bm0 + ar) * K + k0 + ak];
            As[ak + 0][ar] = v.x; As[ak + 1][ar] = v.y;
            As[ak + 2][ar] = v.z; As[ak + 3][ar] = v.w;
        }
        // B tile: 32x32 floats, float4 per thread
        {
            int br = tid >> 3, bc = (tid & 7) * 4;
            *(float4*)&Bs[br][bc] = *(const float4*)&Bw[(size_t)(k0 + br) * N + bn0 + bc];
        }
        __syncthreads();
        #pragma unroll
        for (int k = 0; k < BK; k++) {
            float4 av = *(const float4*)&As[k][ty * 4];
            float b0 = Bs[k][tx * 2], b1 = Bs[k][tx * 2 + 1];
            acc[0][0] = fmaf(av.x, b0, acc[0][0]); acc[0][1] = fmaf(av.x, b1, acc[0][1]);
            acc[1][0] = fmaf(av.y, b0, acc[1][0]); acc[1][1] = fmaf(av.y, b1, acc[1][1]);
            acc[2][0] = fmaf(av.z, b0, acc[2][0]); acc[2][1] = fmaf(av.z, b1, acc[2][1]);
            acc[3][0] = fmaf(av.w, b0, acc[3][0]); acc[3][1] = fmaf(av.w, b1, acc[3][1]);
        }
        __syncthreads();
    }

    int r0 = bm0 + ty * 4;
    #pragma unroll
    for (int i = 0; i < 4; i++) {
        float v0 = acc[i][0], v1 = acc[i][1];
        if (RELU) { v0 = fmaxf(v0, 0.0f); v1 = fmaxf(v1, 0.0f); }
        C[(size_t)(r0 + i) * N + c0]     = v0;
        C[(size_t)(r0 + i) * N + c0 + 1] = v1;
    }
}

// ---------------- launch ----------------
extern "C" void kernel_launch(void* const* d_in, const int* in_sizes, int n_in,
                              void* d_out, int out_size) {
    const float* feat   = (const float*)d_in[0];
    const void*  batch  = d_in[1];                 // int32 or int64, probed on device
    const float* ln_g   = (const float*)d_in[2];
    const float* ln_b   = (const float*)d_in[3];
    const float* proj_w = (const float*)d_in[4];
    const float* proj_b = (const float*)d_in[5];
    const float* w1     = (const float*)d_in[6];
    const float* b1     = (const float*)d_in[7];
    const float* w2     = (const float*)d_in[8];
    const float* b2     = (const float*)d_in[9];
    const float* w3     = (const float*)d_in[10];
    const float* b3     = (const float*)d_in[11];
    float* out = (float*)d_out;
    int n = in_sizes[1];   // number of points

    k_init<<<32, 256>>>();
    k_segmax<<<2048, 256>>>(feat, batch, n);
    k_lnproj<<<NSEG, 64>>>(ln_g, ln_b, proj_w, proj_b);
    k_gemm<0><<<dim3(H1DIM / 32, NSEG / 64), 256>>>(w1, b1, out, H1DIM, LATENT);
    k_gemm<1><<<dim3(H2DIM / 32, NSEG / 64), 256>>>(w2, b2, out, H2DIM, H1DIM);
    k_gemm<2><<<dim3(OUTDIM / 32, NSEG / 64), 256>>>(w3, b3, out, OUTDIM, H2DIM);
}

// round 5
// speedup vs baseline: 1.1404x; 1.1404x over previous
#include <cuda_runtime.h>
#include <cstdint>

#define NSEG 128
#define FEAT 64
#define LATENT 512
#define H1DIM 256
#define H2DIM 512
#define OUTDIM (2048*3)

// ---------------- scratch ----------------
__device__ unsigned g_pool[NSEG * FEAT];
__device__ float    g_lat[NSEG * LATENT];
__device__ float    g_h1[NSEG * H1DIM];
__device__ float    g_h2[NSEG * H2DIM];

// monotonic float<->uint encoding so unsigned atomicMax == float max
__device__ __forceinline__ unsigned ford(float f) {
    unsigned u = __float_as_uint(f);
    return (u & 0x80000000u) ? ~u : (u | 0x80000000u);
}
__device__ __forceinline__ float unford(unsigned u) {
    unsigned b = (u & 0x80000000u) ? (u ^ 0x80000000u) : ~u;
    return __uint_as_float(b);
}

typedef unsigned long long ull;
__device__ __forceinline__ ull pk2(float lo, float hi) {
    ull r; asm("mov.b64 %0, {%1,%2};" : "=l"(r) : "f"(lo), "f"(hi)); return r;
}
__device__ __forceinline__ float2 upk2(ull v) {
    float2 f; asm("mov.b64 {%0,%1}, %2;" : "=f"(f.x), "=f"(f.y) : "l"(v)); return f;
}
__device__ __forceinline__ ull ffma2(ull a, ull b, ull c) {
    ull d; asm("fma.rn.f32x2 %0, %1, %2, %3;" : "=l"(d) : "l"(a), "l"(b), "l"(c)); return d;
}

// ---------------- kernel 0: init pool ----------------
__global__ void k_init() {
    int i = blockIdx.x * blockDim.x + threadIdx.x;
    if (i < NSEG * FEAT) g_pool[i] = 0x007FFFFFu;   // ford(-inf)
}

// ---------------- kernel 1: segment max ----------------
template<bool IS64>
__device__ __forceinline__ void segmax_body(const float* __restrict__ feat,
                                            const void* __restrict__ batch, int n) {
    const int*       b32 = (const int*)batch;
    const long long* b64 = (const long long*)batch;
    int chunk = (n + gridDim.x - 1) / gridDim.x;
    int r0 = blockIdx.x * chunk;
    int r1 = min(n, r0 + chunk);
    int lr = threadIdx.x >> 5;
    int cp = threadIdx.x & 31;
    float mx = __int_as_float(0xff800000), my = mx;
    int cur = -1;
    for (int r = r0 + lr; r < r1; r += 8) {
        int s = IS64 ? (int)b64[r] : b32[r];
        float2 v = ((const float2*)(feat + (size_t)r * FEAT))[cp];
        if (s != cur) {
            if ((unsigned)cur < NSEG) {
                atomicMax(&g_pool[cur * FEAT + 2 * cp],     ford(mx));
                atomicMax(&g_pool[cur * FEAT + 2 * cp + 1], ford(my));
            }
            cur = s; mx = v.x; my = v.y;
        } else {
            mx = fmaxf(mx, v.x); my = fmaxf(my, v.y);
        }
    }
    if ((unsigned)cur < NSEG) {
        atomicMax(&g_pool[cur * FEAT + 2 * cp],     ford(mx));
        atomicMax(&g_pool[cur * FEAT + 2 * cp + 1], ford(my));
    }
}

__global__ void k_segmax(const float* __restrict__ feat,
                         const void* __restrict__ batch, int n) {
    bool is32 = (((const int*)batch)[n - 1] != 0);
    if (is32) segmax_body<false>(feat, batch, n);
    else      segmax_body<true >(feat, batch, n);
}

// ---------------- kernel 2: LayerNorm(64) + proj 64->512 ----------------
__global__ void k_lnproj(const float* __restrict__ lng, const float* __restrict__ lnb,
                         const float* __restrict__ W,   const float* __restrict__ pb) {
    int row = blockIdx.x;
    int t = threadIdx.x;   // 0..63
    __shared__ float xn[FEAT];
    __shared__ float red[4];
    float x = unford(g_pool[row * FEAT + t]);
    float s = x, q = x * x;
    #pragma unroll
    for (int o = 16; o; o >>= 1) {
        s += __shfl_xor_sync(0xffffffffu, s, o);
        q += __shfl_xor_sync(0xffffffffu, q, o);
    }
    if ((t & 31) == 0) { red[t >> 5] = s; red[2 + (t >> 5)] = q; }
    __syncthreads();
    float mu  = (red[0] + red[1]) * (1.0f / FEAT);
    float var = (red[2] + red[3]) * (1.0f / FEAT) - mu * mu;
    float rs  = rsqrtf(var + 1e-5f);
    xn[t] = (x - mu) * rs * lng[t] + lnb[t];
    __syncthreads();
    float acc[8];
    #pragma unroll
    for (int m = 0; m < 8; m++) acc[m] = pb[t + 64 * m];
    #pragma unroll 4
    for (int k = 0; k < FEAT; k++) {
        float xv = xn[k];
        #pragma unroll
        for (int m = 0; m < 8; m++)
            acc[m] = fmaf(xv, W[k * LATENT + t + 64 * m], acc[m]);
    }
    #pragma unroll
    for (int m = 0; m < 8; m++) g_lat[row * LATENT + t + 64 * m] = acc[m];
}

// ---------------- kernel 3: double-buffered f32x2 GEMM ----------------
// C[128,NN] = [relu](A[128,KK] @ Bw[KK,NN] + bias)
// MODE 0: g_lat->g_h1 (relu), 1: g_h1->g_h2 (relu), 2: g_h2->Cout (no relu)
// 256 threads as 16x16; each thread RM x RN outputs (RM=BM/16, RN=BN/16).
template<int MODE, int BM, int BN, int KK, int NN>
__launch_bounds__(256)
__global__ void k_gemm(const float* __restrict__ Bw,
                       const float* __restrict__ bias, float* __restrict__ Cout) {
    constexpr int BK = 32;
    constexpr int RM = BM / 16, RN = BN / 16;     // 2x2 or 4x4
    constexpr int NT = KK / BK;
    constexpr int A4 = BM * BK / 4 / 256;         // float4 A loads per thread
    constexpr int B4 = BK * BN / 4 / 256;
    const float* A = (MODE == 0) ? g_lat : (MODE == 1) ? g_h1 : g_h2;
    float*       C = (MODE == 0) ? g_h1  : (MODE == 1) ? g_h2 : Cout;
    constexpr bool RELU = (MODE != 2);

    __shared__ __align__(16) float As[2][BK][BM];
    __shared__ __align__(16) float Bs[2][BK][BN];

    int tid = threadIdx.x;
    int tx = tid & 15, ty = tid >> 4;
    int bm0 = blockIdx.y * BM, bn0 = blockIdx.x * BN;
    int c0 = bn0 + tx * RN;

    ull acc[RM / 2][RN];
    #pragma unroll
    for (int j = 0; j < RN; j++) {
        float bv = bias[c0 + j];
        ull s = pk2(bv, bv);
        #pragma unroll
        for (int i = 0; i < RM / 2; i++) acc[i][j] = s;
    }

    float4 aReg[A4], bReg[B4];
    // ---- prologue: fetch tile 0 ----
    #pragma unroll
    for (int i = 0; i < A4; i++) {
        int l = tid + i * 256;
        int ar = l / (BK / 4), ak = (l % (BK / 4)) * 4;
        aReg[i] = *(const float4*)&A[(size_t)(bm0 + ar) * KK + ak];
    }
    #pragma unroll
    for (int i = 0; i < B4; i++) {
        int l = tid + i * 256;
        int br = l / (BN / 4), bc = (l % (BN / 4)) * 4;
        bReg[i] = *(const float4*)&Bw[(size_t)br * NN + bn0 + bc];
    }
    #pragma unroll
    for (int i = 0; i < A4; i++) {
        int l = tid + i * 256;
        int ar = l / (BK / 4), ak = (l % (BK / 4)) * 4;
        As[0][ak + 0][ar] = aReg[i].x; As[0][ak + 1][ar] = aReg[i].y;
        As[0][ak + 2][ar] = aReg[i].z; As[0][ak + 3][ar] = aReg[i].w;
    }
    #pragma unroll
    for (int i = 0; i < B4; i++) {
        int l = tid + i * 256;
        int br = l / (BN / 4), bc = (l % (BN / 4)) * 4;
        *(float4*)&Bs[0][br][bc] = bReg[i];
    }
    __syncthreads();

    for (int k0 = 0; k0 < NT; k0++) {
        int cur = k0 & 1, nxt = cur ^ 1;
        if (k0 + 1 < NT) {          // issue next-tile loads (latency overlapped)
            #pragma unroll
            for (int i = 0; i < A4; i++) {
                int l = tid + i * 256;
                int ar = l / (BK / 4), ak = (l % (BK / 4)) * 4;
                aReg[i] = *(const float4*)&A[(size_t)(bm0 + ar) * KK + (k0 + 1) * BK + ak];
            }
            #pragma unroll
            for (int i = 0; i < B4; i++) {
                int l = tid + i * 256;
                int br = l / (BN / 4), bc = (l % (BN / 4)) * 4;
                bReg[i] = *(const float4*)&Bw[(size_t)((k0 + 1) * BK + br) * NN + bn0 + bc];
            }
        }
        // ---- compute on cur ----
        #pragma unroll
        for (int k = 0; k < BK; k++) {
            float a_[RM], b_[RN];
            if (RM == 4) { float4 v = *(const float4*)&As[cur][k][ty * 4];
                           a_[0] = v.x; a_[1] = v.y; a_[2] = v.z; a_[3] = v.w; }
            else         { float2 v = *(const float2*)&As[cur][k][ty * 2];
                           a_[0] = v.x; a_[1] = v.y; }
            if (RN == 4) { float4 v = *(const float4*)&Bs[cur][k][tx * 4];
                           b_[0] = v.x; b_[1] = v.y; b_[2] = v.z; b_[3] = v.w; }
            else         { float2 v = *(const float2*)&Bs[cur][k][tx * 2];
                           b_[0] = v.x; b_[1] = v.y; }
            #pragma unroll
            for (int i = 0; i < RM / 2; i++) {
                ull ap = pk2(a_[2 * i], a_[2 * i + 1]);
                #pragma unroll
                for (int j = 0; j < RN; j++)
                    acc[i][j] = ffma2(ap, pk2(b_[j], b_[j]), acc[i][j]);
            }
        }
        if (k0 + 1 < NT) {          // commit next tile
            #pragma unroll
            for (int i = 0; i < A4; i++) {
                int l = tid + i * 256;
                int ar = l / (BK / 4), ak = (l % (BK / 4)) * 4;
                As[nxt][ak + 0][ar] = aReg[i].x; As[nxt][ak + 1][ar] = aReg[i].y;
                As[nxt][ak + 2][ar] = aReg[i].z; As[nxt][ak + 3][ar] = aReg[i].w;
            }
            #pragma unroll
            for (int i = 0; i < B4; i++) {
                int l = tid + i * 256;
                int br = l / (BN / 4), bc = (l % (BN / 4)) * 4;
                *(float4*)&Bs[nxt][br][bc] = bReg[i];
            }
        }
        __syncthreads();
    }

    // ---- epilogue ----
    int r0 = bm0 + ty * RM;
    #pragma unroll
    for (int i = 0; i < RM / 2; i++) {
        float2 v[RN];
        #pragma unroll
        for (int j = 0; j < RN; j++) {
            v[j] = upk2(acc[i][j]);
            if (RELU) { v[j].x = fmaxf(v[j].x, 0.0f); v[j].y = fmaxf(v[j].y, 0.0f); }
        }
        if (RN == 4) {
            float4 lo = make_float4(v[0].x, v[1].x, v[2].x, v[3].x);
            float4 hi = make_float4(v[0].y, v[1].y, v[2].y, v[3].y);
            *(float4*)&C[(size_t)(r0 + 2 * i)     * NN + c0] = lo;
            *(float4*)&C[(size_t)(r0 + 2 * i + 1) * NN + c0] = hi;
        } else {
            float2 lo = make_float2(v[0].x, v[1].x);
            float2 hi = make_float2(v[0].y, v[1].y);
            *(float2*)&C[(size_t)(r0 + 2 * i)     * NN + c0] = lo;
            *(float2*)&C[(size_t)(r0 + 2 * i + 1) * NN + c0] = hi;
        }
    }
}

// ---------------- launch ----------------
extern "C" void kernel_launch(void* const* d_in, const int* in_sizes, int n_in,
                              void* d_out, int out_size) {
    const float* feat   = (const float*)d_in[0];
    const void*  batch  = d_in[1];
    const float* ln_g   = (const float*)d_in[2];
    const float* ln_b   = (const float*)d_in[3];
    const float* proj_w = (const float*)d_in[4];
    const float* proj_b = (const float*)d_in[5];
    const float* w1     = (const float*)d_in[6];
    const float* b1     = (const float*)d_in[7];
    const float* w2     = (const float*)d_in[8];
    const float* b2     = (const float*)d_in[9];
    const float* w3     = (const float*)d_in[10];
    const float* b3     = (const float*)d_in[11];
    float* out = (float*)d_out;
    int n = in_sizes[1];

    k_init<<<32, 256>>>();
    k_segmax<<<2048, 256>>>(feat, batch, n);
    k_lnproj<<<NSEG, 64>>>(ln_g, ln_b, proj_w, proj_b);
    k_gemm<0, 32, 32, LATENT, H1DIM><<<dim3(H1DIM / 32, 4), 256>>>(w1, b1, out);
    k_gemm<1, 32, 32, H1DIM, H2DIM><<<dim3(H2DIM / 32, 4), 256>>>(w2, b2, out);
    k_gemm<2, 64, 64, H2DIM, OUTDIM><<<dim3(OUTDIM / 64, 2), 256>>>(w3, b3, out);
}